// round 1
// baseline (speedup 1.0000x reference)
#include <cuda_runtime.h>
#include <cuda_bf16.h>

// Problem constants (fixed by the dataset)
#define NUSER 50000
#define NITEM 50000
#define NN    100000        // total nodes
#define NNZE  1000000       // edges
#define EPSV  1e-12f

// ---------------- scratch (device globals; no allocation allowed) ----------
__device__ int    g_deg[NN];
__device__ int    g_rowptr[NN + 1];
__device__ int    g_cursor[NN];
__device__ int    g_heads[NNZE];      // sorted-by-head edge list (head)
__device__ int    g_tails[NNZE];      // sorted-by-head edge list (tail)
__device__ float4 g_A[NNZE];          // routing logits per edge (sorted order)
__device__ float4 g_vals[NNZE];       // softmax(A) per edge
__device__ float4 g_rowsum[NN];       // per-node, per-factor value row sums
__device__ float4 g_d[NN];            // 1/sqrt(rowsum)
__device__ float4 g_buf0[NN * 16];    // ego / hn ping
__device__ float4 g_buf1[NN * 16];    // ego / hn pong
__device__ float4 g_tt[NN * 16];      // tanh(l2norm(xs)) table (per layer)
__device__ float4 g_acc[NN * 16];     // running sum of layer embeddings

// ---------------- CSR build --------------------------------------------------
__global__ void k_zero_deg() {
    int i = blockIdx.x * blockDim.x + threadIdx.x;
    if (i < NN) g_deg[i] = 0;
}

__global__ void k_hist(const int* __restrict__ head) {
    int e = blockIdx.x * blockDim.x + threadIdx.x;
    if (e < NNZE) atomicAdd(&g_deg[head[e]], 1);
}

// single-block scan over NN degrees -> rowptr + cursor
__global__ void k_scan() {
    const int T = 1024;
    const int CHUNK = (NN + T - 1) / T;   // 98
    __shared__ int ssum[T];
    int t = threadIdx.x;
    int beg = t * CHUNK;
    int end = min(beg + CHUNK, NN);
    int s = 0;
    for (int i = beg; i < end; i++) s += g_deg[i];
    ssum[t] = s;
    __syncthreads();
    // inclusive Hillis-Steele scan
    for (int off = 1; off < T; off <<= 1) {
        int v = 0;
        if (t >= off) v = ssum[t - off];
        __syncthreads();
        if (t >= off) ssum[t] += v;
        __syncthreads();
    }
    int run = ssum[t] - s;   // exclusive prefix for this thread's chunk
    for (int i = beg; i < end; i++) {
        g_rowptr[i] = run;
        g_cursor[i] = run;
        run += g_deg[i];
    }
    if (t == T - 1) g_rowptr[NN] = ssum[T - 1];
}

__global__ void k_scatter(const int* __restrict__ head, const int* __restrict__ tail) {
    int e = blockIdx.x * blockDim.x + threadIdx.x;
    if (e >= NNZE) return;
    int h = head[e];
    int pos = atomicAdd(&g_cursor[h], 1);
    g_heads[pos] = h;
    g_tails[pos] = tail[e];
}

// ---------------- init: ego0 = concat(user,item); acc = ego0 ----------------
__global__ void k_init(const float* __restrict__ user, const float* __restrict__ item) {
    int i = blockIdx.x * blockDim.x + threadIdx.x;   // over NN*16 (exact grid)
    int n = i >> 4, c = i & 15;
    const float* src = (n < NUSER) ? (user + (size_t)n * 64 + c * 4)
                                   : (item + (size_t)(n - NUSER) * 64 + c * 4);
    float4 v = *reinterpret_cast<const float4*>(src);
    g_buf0[i] = v;
    g_acc[i]  = v;
}

// ---------------- tt = tanh(l2norm(xs per factor)) --------------------------
__global__ void k_tt(int xsel) {
    int i = blockIdx.x * blockDim.x + threadIdx.x;   // over NN*4
    if (i >= NN * 4) return;
    int n = i >> 2, f = i & 3;
    const float4* xs = xsel ? g_buf1 : g_buf0;
    int base = n * 16 + f * 4;
    float4 v0 = xs[base + 0], v1 = xs[base + 1], v2 = xs[base + 2], v3 = xs[base + 3];
    float ss = v0.x*v0.x + v0.y*v0.y + v0.z*v0.z + v0.w*v0.w
             + v1.x*v1.x + v1.y*v1.y + v1.z*v1.z + v1.w*v1.w
             + v2.x*v2.x + v2.y*v2.y + v2.z*v2.z + v2.w*v2.w
             + v3.x*v3.x + v3.y*v3.y + v3.z*v3.z + v3.w*v3.w;
    float inv = 1.f / fmaxf(sqrtf(ss), EPSV);
    g_tt[base + 0] = make_float4(tanhf(v0.x*inv), tanhf(v0.y*inv), tanhf(v0.z*inv), tanhf(v0.w*inv));
    g_tt[base + 1] = make_float4(tanhf(v1.x*inv), tanhf(v1.y*inv), tanhf(v1.z*inv), tanhf(v1.w*inv));
    g_tt[base + 2] = make_float4(tanhf(v2.x*inv), tanhf(v2.y*inv), tanhf(v2.z*inv), tanhf(v2.w*inv));
    g_tt[base + 3] = make_float4(tanhf(v3.x*inv), tanhf(v3.y*inv), tanhf(v3.z*inv), tanhf(v3.w*inv));
}

// ---------------- per-iteration kernels --------------------------------------
__global__ void k_zero_rowsum() {
    int i = blockIdx.x * blockDim.x + threadIdx.x;
    if (i < NN * 4) reinterpret_cast<float*>(g_rowsum)[i] = 0.f;
}

__global__ void k_softmax_rowsum(int first) {
    int e = blockIdx.x * blockDim.x + threadIdx.x;
    if (e >= NNZE) return;
    float4 v;
    if (first) {
        v = make_float4(0.25f, 0.25f, 0.25f, 0.25f);
    } else {
        float4 a = g_A[e];
        float m = fmaxf(fmaxf(a.x, a.y), fmaxf(a.z, a.w));
        float e0 = __expf(a.x - m), e1 = __expf(a.y - m);
        float e2 = __expf(a.z - m), e3 = __expf(a.w - m);
        float r = 1.f / (e0 + e1 + e2 + e3);
        v = make_float4(e0 * r, e1 * r, e2 * r, e3 * r);
    }
    g_vals[e] = v;
    float* rs = reinterpret_cast<float*>(&g_rowsum[g_heads[e]]);
    atomicAdd(rs + 0, v.x);
    atomicAdd(rs + 1, v.y);
    atomicAdd(rs + 2, v.z);
    atomicAdd(rs + 3, v.w);
}

__global__ void k_dcalc() {
    int i = blockIdx.x * blockDim.x + threadIdx.x;
    if (i >= NN * 4) return;
    float rs = reinterpret_cast<const float*>(g_rowsum)[i];
    reinterpret_cast<float*>(g_d)[i] = (rs > 0.f) ? (1.f / sqrtf(fmaxf(rs, EPSV))) : 0.f;
}

// fused: CSR spmm (D A D x) + per-factor l2-normalize -> hn; optional acc +=
__global__ void k_spmm_norm(int xsel, int accum) {
    int gid = blockIdx.x * blockDim.x + threadIdx.x;   // NN*16 exact
    int g = gid >> 4, c = gid & 15, f = c >> 2;
    const float4* xs = xsel ? g_buf1 : g_buf0;
    float4*       hn = xsel ? g_buf0 : g_buf1;
    const float* valsF = reinterpret_cast<const float*>(g_vals);
    const float* dF    = reinterpret_cast<const float*>(g_d);
    int beg = g_rowptr[g], end = g_rowptr[g + 1];
    float ax = 0.f, ay = 0.f, az = 0.f, aw = 0.f;
    for (int j = beg; j < end; j++) {
        int t = g_tails[j];
        float s = valsF[j * 4 + f] * dF[t * 4 + f];
        float4 x = xs[t * 16 + c];
        ax = fmaf(s, x.x, ax); ay = fmaf(s, x.y, ay);
        az = fmaf(s, x.z, az); aw = fmaf(s, x.w, aw);
    }
    float dn = dF[g * 4 + f];
    float fx = dn * ax, fy = dn * ay, fz = dn * az, fw = dn * aw;
    float ss = fx*fx + fy*fy + fz*fz + fw*fw;
    ss += __shfl_xor_sync(0xffffffffu, ss, 1);
    ss += __shfl_xor_sync(0xffffffffu, ss, 2);
    float inv = 1.f / fmaxf(sqrtf(ss), EPSV);
    float4 h = make_float4(fx * inv, fy * inv, fz * inv, fw * inv);
    hn[gid] = h;
    if (accum) {
        float4 a = g_acc[gid];
        g_acc[gid] = make_float4(a.x + h.x, a.y + h.y, a.z + h.z, a.w + h.w);
    }
}

// routing scores: A[e,f] += <hn[head], tt[tail]> per factor
__global__ void k_scores(int xsel, int first) {
    int gid = blockIdx.x * blockDim.x + threadIdx.x;   // NNZE*16 exact
    int e = gid >> 4, c = gid & 15;
    int h = g_heads[e], t = g_tails[e];
    const float4* hn = xsel ? g_buf0 : g_buf1;         // buffer written by k_spmm_norm
    float4 a = hn[h * 16 + c];
    float4 b = g_tt[t * 16 + c];
    float p = a.x*b.x + a.y*b.y + a.z*b.z + a.w*b.w;
    p += __shfl_xor_sync(0xffffffffu, p, 1);
    p += __shfl_xor_sync(0xffffffffu, p, 2);
    if ((c & 3) == 0) {
        int f = c >> 2;
        float* A = reinterpret_cast<float*>(g_A);
        float old = first ? 1.f : A[e * 4 + f];
        A[e * 4 + f] = old + p;
    }
}

__global__ void k_out(float* __restrict__ out) {
    int i = blockIdx.x * blockDim.x + threadIdx.x;   // NN*16 exact
    float4 v = g_acc[i];
    const float k = 1.f / 3.f;
    reinterpret_cast<float4*>(out)[i] = make_float4(v.x * k, v.y * k, v.z * k, v.w * k);
}

// ---------------- launch ------------------------------------------------------
extern "C" void kernel_launch(void* const* d_in, const int* in_sizes, int n_in,
                              void* d_out, int out_size) {
    const float* user = (const float*)d_in[0];
    const float* item = (const float*)d_in[1];
    const int*   head = (const int*)d_in[2];
    const int*   tail = (const int*)d_in[3];
    float* out = (float*)d_out;

    const int TB = 256;
    const int gN    = (NN + TB - 1) / TB;
    const int gN4   = (NN * 4 + TB - 1) / TB;
    const int gN16  = (NN * 16) / TB;        // exact
    const int gE    = (NNZE + TB - 1) / TB;
    const int gE16  = (NNZE * 16) / TB;      // exact

    // CSR build (per-launch; deterministic up to within-row order)
    k_zero_deg<<<gN, TB>>>();
    k_hist<<<gE, TB>>>(head);
    k_scan<<<1, 1024>>>();
    k_scatter<<<gE, TB>>>(head, tail);

    // ego0 + accumulator
    k_init<<<gN16, TB>>>(user, item);

    int first = 1;
    for (int layer = 0; layer < 2; layer++) {
        int xsel = layer & 1;               // layer0 reads buf0 writes buf1; layer1 reverse
        k_tt<<<gN4, TB>>>(xsel);
        for (int t = 0; t < 2; t++) {
            k_zero_rowsum<<<gN4, TB>>>();
            k_softmax_rowsum<<<gE, TB>>>(first);
            k_dcalc<<<gN4, TB>>>();
            int accum = (t == 1);
            k_spmm_norm<<<gN16, TB>>>(xsel, accum);
            int last = (layer == 1 && t == 1);
            if (!last) k_scores<<<gE16, TB>>>(xsel, first);
            first = 0;
        }
    }
    k_out<<<gN16, TB>>>(out);
}

// round 2
// speedup vs baseline: 1.1188x; 1.1188x over previous
#include <cuda_runtime.h>
#include <cuda_bf16.h>

#define NUSER 50000
#define NN    100000        // total nodes
#define NNZE  1000000       // edges
#define EPSV  1e-12f

// ---------------- scratch (device globals) -----------------------------------
__device__ int    g_deg[NN];
__device__ int    g_rowptr[NN + 1];
__device__ int    g_cursor[NN];
__device__ int    g_heads[NNZE];      // sorted-by-head
__device__ int    g_tails[NNZE];
__device__ float4 g_A[NNZE];          // routing logits (sorted edge order)
__device__ float4 g_vals[NNZE];       // softmax(A)
__device__ float  g_d[NN * 4];        // 1/sqrt(rowsum) per (node,factor)
__device__ float4 g_buf0[NN * 16];    // ego / hn ping
__device__ float4 g_buf1[NN * 16];    // ego / hn pong
__device__ float4 g_tt[NN * 16];      // tanh(l2norm(xs)) for current layer
__device__ float4 g_acc[NN * 16];     // running sum of layer embeddings

// ---------------- CSR build ---------------------------------------------------
__global__ void k_zero_deg() {
    int i = blockIdx.x * blockDim.x + threadIdx.x;
    if (i < NN) g_deg[i] = 0;
}

__global__ void k_hist(const int* __restrict__ head) {
    int e = blockIdx.x * blockDim.x + threadIdx.x;
    if (e < NNZE) atomicAdd(&g_deg[head[e]], 1);
}

__global__ void k_scan() {
    const int T = 1024;
    const int CHUNK = (NN + T - 1) / T;
    __shared__ int ssum[T];
    int t = threadIdx.x;
    int beg = t * CHUNK;
    int end = min(beg + CHUNK, NN);
    int s = 0;
    for (int i = beg; i < end; i++) s += g_deg[i];
    ssum[t] = s;
    __syncthreads();
    for (int off = 1; off < T; off <<= 1) {
        int v = 0;
        if (t >= off) v = ssum[t - off];
        __syncthreads();
        if (t >= off) ssum[t] += v;
        __syncthreads();
    }
    int run = ssum[t] - s;
    for (int i = beg; i < end; i++) {
        g_rowptr[i] = run;
        g_cursor[i] = run;
        run += g_deg[i];
    }
    if (t == T - 1) g_rowptr[NN] = ssum[T - 1];
}

__global__ void k_scatter(const int* __restrict__ head, const int* __restrict__ tail) {
    int e = blockIdx.x * blockDim.x + threadIdx.x;
    if (e >= NNZE) return;
    int h = head[e];
    int pos = atomicAdd(&g_cursor[h], 1);
    g_heads[pos] = h;
    g_tails[pos] = tail[e];
}

// ---------------- init: ego0, acc, tt (for layer 0) ---------------------------
__global__ void k_init(const float* __restrict__ user, const float* __restrict__ item) {
    int i = blockIdx.x * blockDim.x + threadIdx.x;   // NN*16 exact
    int n = i >> 4, c = i & 15;
    const float* src = (n < NUSER) ? (user + (size_t)n * 64 + c * 4)
                                   : (item + (size_t)(n - NUSER) * 64 + c * 4);
    float4 v = *reinterpret_cast<const float4*>(src);
    g_buf0[i] = v;
    g_acc[i]  = v;
    // per-factor l2 norm: chunks of a factor are 4 consecutive lanes
    float ss = v.x*v.x + v.y*v.y + v.z*v.z + v.w*v.w;
    ss += __shfl_xor_sync(0xffffffffu, ss, 1);
    ss += __shfl_xor_sync(0xffffffffu, ss, 2);
    float inv = 1.f / fmaxf(sqrtf(ss), EPSV);
    g_tt[i] = make_float4(tanhf(v.x*inv), tanhf(v.y*inv), tanhf(v.z*inv), tanhf(v.w*inv));
}

// tt = tanh(hn): hn is already per-factor unit-norm, so l2norm is identity
__global__ void k_tt_from_hn(int xsel) {
    int i = blockIdx.x * blockDim.x + threadIdx.x;   // NN*16 exact
    const float4* hn = xsel ? g_buf0 : g_buf1;
    float4 h = hn[i];
    g_tt[i] = make_float4(tanhf(h.x), tanhf(h.y), tanhf(h.z), tanhf(h.w));
}

// ---------------- per-iteration kernels ---------------------------------------
// CSR segment-sum of softmax values -> d = 1/sqrt(rowsum). No atomics.
__global__ void k_rowsum_d(int first) {
    int i = blockIdx.x * blockDim.x + threadIdx.x;
    if (i >= NN * 4) return;
    int g = i >> 2, f = i & 3;
    int beg = g_rowptr[g], end = g_rowptr[g + 1];
    float s;
    if (first) {
        s = 0.25f * (float)(end - beg);
    } else {
        const float* v = reinterpret_cast<const float*>(g_vals);
        s = 0.f;
        for (int j = beg; j < end; j++) s += v[j * 4 + f];
    }
    g_d[i] = (s > 0.f) ? (1.f / sqrtf(fmaxf(s, EPSV))) : 0.f;
}

// fused: CSR spmm (D A D x) + per-factor l2-normalize
// mode 0: write hn
// mode 1: write hn and acc += h           (layer-0 end)
// mode 2: write out = (acc + h) / 3       (layer-1 end, final)
__global__ void k_spmm_norm(int xsel, int first, int mode, float* __restrict__ out) {
    int gid = blockIdx.x * blockDim.x + threadIdx.x;   // NN*16 exact
    int g = gid >> 4, c = gid & 15, f = c >> 2;
    const float4* xs = xsel ? g_buf1 : g_buf0;
    float4*       hn = xsel ? g_buf0 : g_buf1;
    const float* valsF = reinterpret_cast<const float*>(g_vals);
    int beg = g_rowptr[g], end = g_rowptr[g + 1];
    float ax = 0.f, ay = 0.f, az = 0.f, aw = 0.f;
    int j = beg;
    // unroll-by-2 for doubled memory-level parallelism
    for (; j + 1 < end; j += 2) {
        int t0 = g_tails[j], t1 = g_tails[j + 1];
        float w0 = first ? 0.25f : valsF[j * 4 + f];
        float w1 = first ? 0.25f : valsF[(j + 1) * 4 + f];
        float s0 = w0 * g_d[t0 * 4 + f];
        float s1 = w1 * g_d[t1 * 4 + f];
        float4 x0 = xs[t0 * 16 + c];
        float4 x1 = xs[t1 * 16 + c];
        ax = fmaf(s0, x0.x, ax); ay = fmaf(s0, x0.y, ay);
        az = fmaf(s0, x0.z, az); aw = fmaf(s0, x0.w, aw);
        ax = fmaf(s1, x1.x, ax); ay = fmaf(s1, x1.y, ay);
        az = fmaf(s1, x1.z, az); aw = fmaf(s1, x1.w, aw);
    }
    if (j < end) {
        int t = g_tails[j];
        float w = first ? 0.25f : valsF[j * 4 + f];
        float s = w * g_d[t * 4 + f];
        float4 x = xs[t * 16 + c];
        ax = fmaf(s, x.x, ax); ay = fmaf(s, x.y, ay);
        az = fmaf(s, x.z, az); aw = fmaf(s, x.w, aw);
    }
    float dn = g_d[g * 4 + f];
    float fx = dn * ax, fy = dn * ay, fz = dn * az, fw = dn * aw;
    float ss = fx*fx + fy*fy + fz*fz + fw*fw;
    ss += __shfl_xor_sync(0xffffffffu, ss, 1);
    ss += __shfl_xor_sync(0xffffffffu, ss, 2);
    float inv = 1.f / fmaxf(sqrtf(ss), EPSV);
    float4 h = make_float4(fx * inv, fy * inv, fz * inv, fw * inv);
    if (mode == 2) {
        float4 a = g_acc[gid];
        const float k = 1.f / 3.f;
        reinterpret_cast<float4*>(out)[gid] =
            make_float4((a.x + h.x) * k, (a.y + h.y) * k, (a.z + h.z) * k, (a.w + h.w) * k);
    } else {
        hn[gid] = h;
        if (mode == 1) {
            float4 a = g_acc[gid];
            g_acc[gid] = make_float4(a.x + h.x, a.y + h.y, a.z + h.z, a.w + h.w);
        }
    }
}

// fused routing scores + A update + softmax -> vals for next iteration
__global__ void k_scores(int xsel, int first) {
    int gid = blockIdx.x * blockDim.x + threadIdx.x;   // NNZE*16 exact
    int e = gid >> 4, c = gid & 15;
    int h = g_heads[e], t = g_tails[e];
    const float4* hn = xsel ? g_buf0 : g_buf1;
    float4 a = hn[h * 16 + c];
    float4 b = g_tt[t * 16 + c];
    float p = a.x*b.x + a.y*b.y + a.z*b.z + a.w*b.w;
    p += __shfl_xor_sync(0xffffffffu, p, 1);
    p += __shfl_xor_sync(0xffffffffu, p, 2);
    // gather the 4 factor scores (lanes base+0,4,8,12 within the 16-lane group)
    int lane = threadIdx.x & 31;
    int base = lane & 16;
    float s0 = __shfl_sync(0xffffffffu, p, base + 0);
    float s1 = __shfl_sync(0xffffffffu, p, base + 4);
    float s2 = __shfl_sync(0xffffffffu, p, base + 8);
    float s3 = __shfl_sync(0xffffffffu, p, base + 12);
    if (c == 0) {
        float4 A = first ? make_float4(1.f, 1.f, 1.f, 1.f) : g_A[e];
        A.x += s0; A.y += s1; A.z += s2; A.w += s3;
        g_A[e] = A;
        float m = fmaxf(fmaxf(A.x, A.y), fmaxf(A.z, A.w));
        float e0 = __expf(A.x - m), e1 = __expf(A.y - m);
        float e2 = __expf(A.z - m), e3 = __expf(A.w - m);
        float r = 1.f / (e0 + e1 + e2 + e3);
        g_vals[e] = make_float4(e0 * r, e1 * r, e2 * r, e3 * r);
    }
}

// ---------------- launch -------------------------------------------------------
extern "C" void kernel_launch(void* const* d_in, const int* in_sizes, int n_in,
                              void* d_out, int out_size) {
    const float* user = (const float*)d_in[0];
    const float* item = (const float*)d_in[1];
    const int*   head = (const int*)d_in[2];
    const int*   tail = (const int*)d_in[3];
    float* out = (float*)d_out;

    const int TB = 256;
    const int gN    = (NN + TB - 1) / TB;
    const int gN4   = (NN * 4 + TB - 1) / TB;
    const int gN16  = (NN * 16) / TB;        // exact
    const int gE    = (NNZE + TB - 1) / TB;
    const int gE16  = (NNZE * 16) / TB;      // exact

    // CSR build
    k_zero_deg<<<gN, TB>>>();
    k_hist<<<gE, TB>>>(head);
    k_scan<<<1, 1024>>>();
    k_scatter<<<gE, TB>>>(head, tail);

    // ego0 + acc + tt(layer 0)
    k_init<<<gN16, TB>>>(user, item);

    // ---- layer 0 (xs = buf0, hn = buf1) ----
    k_rowsum_d<<<gN4, TB>>>(1);
    k_spmm_norm<<<gN16, TB>>>(0, 1, 0, out);
    k_scores<<<gE16, TB>>>(0, 1);            // A = 1 + s, vals = softmax(A)
    k_rowsum_d<<<gN4, TB>>>(0);
    k_spmm_norm<<<gN16, TB>>>(0, 0, 1, out); // hn + acc
    k_scores<<<gE16, TB>>>(0, 0);            // uses layer-0 tt (still intact)
    k_tt_from_hn<<<gN16, TB>>>(0);           // tt for layer 1 = tanh(hn=buf1)

    // ---- layer 1 (xs = buf1, hn = buf0) ----
    k_rowsum_d<<<gN4, TB>>>(0);
    k_spmm_norm<<<gN16, TB>>>(1, 0, 0, out);
    k_scores<<<gE16, TB>>>(1, 0);
    k_rowsum_d<<<gN4, TB>>>(0);
    k_spmm_norm<<<gN16, TB>>>(1, 0, 2, out); // out = (acc + h)/3
}

// round 3
// speedup vs baseline: 1.2144x; 1.0855x over previous
#include <cuda_runtime.h>
#include <cuda_bf16.h>

#define NUSER 50000
#define NN    100000        // total nodes
#define NNZE  1000000       // edges
#define EPSV  1e-12f

// ---------------- scratch (device globals) -----------------------------------
__device__ int    g_deg[NN];
__device__ int    g_rowptr[NN + 1];
__device__ int    g_cursor[NN];
__device__ int    g_tails[NNZE];      // sorted-by-head tail list
__device__ float4 g_A[NNZE];          // routing logits (sorted edge order)
__device__ float4 g_vals[NNZE];       // softmax(A)
__device__ float  g_d0[NN * 4];       // 1/sqrt(rowsum) ping
__device__ float  g_d1[NN * 4];       // 1/sqrt(rowsum) pong
__device__ float4 g_buf0[NN * 16];    // ego / hn ping
__device__ float4 g_buf1[NN * 16];    // ego / hn pong
__device__ float4 g_tt0[NN * 16];     // tanh(l2norm(xs)) for layer 0
__device__ float4 g_tt1[NN * 16];     // tanh(l2norm(xs)) for layer 1
__device__ float4 g_acc[NN * 16];     // running sum of layer embeddings

// ---------------- CSR build ---------------------------------------------------
__global__ void k_zero_deg() {
    int i = blockIdx.x * blockDim.x + threadIdx.x;
    if (i < NN) g_deg[i] = 0;
}

__global__ void k_hist(const int* __restrict__ head) {
    int e = blockIdx.x * blockDim.x + threadIdx.x;
    if (e < NNZE) atomicAdd(&g_deg[head[e]], 1);
}

__global__ void k_scan() {
    const int T = 1024;
    const int CHUNK = (NN + T - 1) / T;
    __shared__ int ssum[T];
    int t = threadIdx.x;
    int beg = t * CHUNK;
    int end = min(beg + CHUNK, NN);
    int s = 0;
    for (int i = beg; i < end; i++) s += g_deg[i];
    ssum[t] = s;
    __syncthreads();
    for (int off = 1; off < T; off <<= 1) {
        int v = 0;
        if (t >= off) v = ssum[t - off];
        __syncthreads();
        if (t >= off) ssum[t] += v;
        __syncthreads();
    }
    int run = ssum[t] - s;
    for (int i = beg; i < end; i++) {
        g_rowptr[i] = run;
        g_cursor[i] = run;
        run += g_deg[i];
    }
    if (t == T - 1) g_rowptr[NN] = ssum[T - 1];
}

__global__ void k_scatter(const int* __restrict__ head, const int* __restrict__ tail) {
    int e = blockIdx.x * blockDim.x + threadIdx.x;
    if (e >= NNZE) return;
    int pos = atomicAdd(&g_cursor[head[e]], 1);
    g_tails[pos] = tail[e];
}

// ---------------- init: ego0, acc, tt0 ----------------------------------------
__global__ void k_init(const float* __restrict__ user, const float* __restrict__ item) {
    int i = blockIdx.x * blockDim.x + threadIdx.x;   // NN*16 exact
    int n = i >> 4, c = i & 15;
    const float* src = (n < NUSER) ? (user + (size_t)n * 64 + c * 4)
                                   : (item + (size_t)(n - NUSER) * 64 + c * 4);
    float4 v = *reinterpret_cast<const float4*>(src);
    g_buf0[i] = v;
    g_acc[i]  = v;
    float ss = v.x*v.x + v.y*v.y + v.z*v.z + v.w*v.w;
    ss += __shfl_xor_sync(0xffffffffu, ss, 1);
    ss += __shfl_xor_sync(0xffffffffu, ss, 2);
    float inv = 1.f / fmaxf(sqrtf(ss), EPSV);
    g_tt0[i] = make_float4(tanhf(v.x*inv), tanhf(v.y*inv), tanhf(v.z*inv), tanhf(v.w*inv));
}

// first-iteration d: rowsum = 0.25 * degree
__global__ void k_dinit() {
    int i = blockIdx.x * blockDim.x + threadIdx.x;
    if (i >= NN * 4) return;
    int g = i >> 2;
    float s = 0.25f * (float)(g_rowptr[g + 1] - g_rowptr[g]);
    g_d0[i] = (s > 0.f) ? (1.f / sqrtf(fmaxf(s, EPSV))) : 0.f;
}

// ---------------- the whole routing iteration in one kernel -------------------
// loop1: h = l2norm(D A D x) per factor      (gather xs[tail], d[tail], vals)
// loop2: scores s[e,f] = <h_f, tt[tail]_f>; A += s; vals = softmax(A);
//        accumulate next rowsum -> d_next    (gather tt[tail] only)
// mode 0: write hn, do scores
// mode 1: write hn, acc += h, tt1 = tanh(h), do scores    (layer-0 end)
// mode 2: write out = (acc + h)/3, NO scores               (final)
__global__ void k_fused(int xsel, int dsel, int ttsel, int first, int mode,
                        float* __restrict__ out) {
    int gid = blockIdx.x * blockDim.x + threadIdx.x;   // NN*16 exact
    int g = gid >> 4, c = gid & 15, f = c >> 2;
    const float4* xs = xsel ? g_buf1 : g_buf0;
    float4*       hn = xsel ? g_buf0 : g_buf1;
    const float*  dcur  = dsel ? g_d1 : g_d0;
    float*        dnext = dsel ? g_d0 : g_d1;
    const float4* tt = ttsel ? g_tt1 : g_tt0;
    const float* valsF = reinterpret_cast<const float*>(g_vals);
    int beg = g_rowptr[g], end = g_rowptr[g + 1];

    // ---- loop 1: weighted gather ----
    float ax = 0.f, ay = 0.f, az = 0.f, aw = 0.f;
    int j = beg;
    for (; j + 1 < end; j += 2) {
        int t0 = g_tails[j], t1 = g_tails[j + 1];
        float w0 = first ? 0.25f : valsF[j * 4 + f];
        float w1 = first ? 0.25f : valsF[(j + 1) * 4 + f];
        float s0 = w0 * dcur[t0 * 4 + f];
        float s1 = w1 * dcur[t1 * 4 + f];
        float4 x0 = xs[t0 * 16 + c];
        float4 x1 = xs[t1 * 16 + c];
        ax = fmaf(s0, x0.x, ax); ay = fmaf(s0, x0.y, ay);
        az = fmaf(s0, x0.z, az); aw = fmaf(s0, x0.w, aw);
        ax = fmaf(s1, x1.x, ax); ay = fmaf(s1, x1.y, ay);
        az = fmaf(s1, x1.z, az); aw = fmaf(s1, x1.w, aw);
    }
    if (j < end) {
        int t = g_tails[j];
        float w = first ? 0.25f : valsF[j * 4 + f];
        float s = w * dcur[t * 4 + f];
        float4 x = xs[t * 16 + c];
        ax = fmaf(s, x.x, ax); ay = fmaf(s, x.y, ay);
        az = fmaf(s, x.z, az); aw = fmaf(s, x.w, aw);
    }
    float dn = dcur[g * 4 + f];
    float fx = dn * ax, fy = dn * ay, fz = dn * az, fw = dn * aw;
    float ss = fx*fx + fy*fy + fz*fz + fw*fw;
    ss += __shfl_xor_sync(0xffffffffu, ss, 1);
    ss += __shfl_xor_sync(0xffffffffu, ss, 2);
    float inv = 1.f / fmaxf(sqrtf(ss), EPSV);
    float4 h = make_float4(fx * inv, fy * inv, fz * inv, fw * inv);

    if (mode == 2) {
        float4 a = g_acc[gid];
        const float k = 1.f / 3.f;
        reinterpret_cast<float4*>(out)[gid] =
            make_float4((a.x + h.x) * k, (a.y + h.y) * k, (a.z + h.z) * k, (a.w + h.w) * k);
        return;
    }
    hn[gid] = h;
    if (mode == 1) {
        float4 a = g_acc[gid];
        g_acc[gid] = make_float4(a.x + h.x, a.y + h.y, a.z + h.z, a.w + h.w);
        g_tt1[gid] = make_float4(tanhf(h.x), tanhf(h.y), tanhf(h.z), tanhf(h.w));
    }

    // ---- loop 2: routing scores + softmax + next-iteration rowsum ----
    // groups of 16 lanes; masks restricted to the group (rows in the same warp
    // can have different lengths, so full-warp masks would be illegal here)
    unsigned gbase = threadIdx.x & 16;          // 0 or 16
    unsigned gmask = 0xFFFFu << gbase;
    float rs0 = 0.f, rs1 = 0.f, rs2 = 0.f, rs3 = 0.f;
    for (j = beg; j < end; j++) {
        int t = g_tails[j];
        float4 b = tt[t * 16 + c];
        float p = h.x*b.x + h.y*b.y + h.z*b.z + h.w*b.w;
        p += __shfl_xor_sync(gmask, p, 1);
        p += __shfl_xor_sync(gmask, p, 2);
        float s0 = __shfl_sync(gmask, p, gbase + 0);
        float s1 = __shfl_sync(gmask, p, gbase + 4);
        float s2 = __shfl_sync(gmask, p, gbase + 8);
        float s3 = __shfl_sync(gmask, p, gbase + 12);
        if (c == 0) {
            float4 A = first ? make_float4(1.f, 1.f, 1.f, 1.f) : g_A[j];
            A.x += s0; A.y += s1; A.z += s2; A.w += s3;
            g_A[j] = A;
            float m = fmaxf(fmaxf(A.x, A.y), fmaxf(A.z, A.w));
            float e0 = __expf(A.x - m), e1 = __expf(A.y - m);
            float e2 = __expf(A.z - m), e3 = __expf(A.w - m);
            float r = 1.f / (e0 + e1 + e2 + e3);
            float4 v = make_float4(e0 * r, e1 * r, e2 * r, e3 * r);
            g_vals[j] = v;
            rs0 += v.x; rs1 += v.y; rs2 += v.z; rs3 += v.w;
        }
    }
    if (c == 0) {
        dnext[g * 4 + 0] = (rs0 > 0.f) ? (1.f / sqrtf(fmaxf(rs0, EPSV))) : 0.f;
        dnext[g * 4 + 1] = (rs1 > 0.f) ? (1.f / sqrtf(fmaxf(rs1, EPSV))) : 0.f;
        dnext[g * 4 + 2] = (rs2 > 0.f) ? (1.f / sqrtf(fmaxf(rs2, EPSV))) : 0.f;
        dnext[g * 4 + 3] = (rs3 > 0.f) ? (1.f / sqrtf(fmaxf(rs3, EPSV))) : 0.f;
    }
}

// ---------------- launch -------------------------------------------------------
extern "C" void kernel_launch(void* const* d_in, const int* in_sizes, int n_in,
                              void* d_out, int out_size) {
    const float* user = (const float*)d_in[0];
    const float* item = (const float*)d_in[1];
    const int*   head = (const int*)d_in[2];
    const int*   tail = (const int*)d_in[3];
    float* out = (float*)d_out;

    const int TB = 256;
    const int gN   = (NN + TB - 1) / TB;
    const int gN4  = (NN * 4 + TB - 1) / TB;
    const int gN16 = (NN * 16) / TB;        // exact
    const int gE   = (NNZE + TB - 1) / TB;

    // CSR build
    k_zero_deg<<<gN, TB>>>();
    k_hist<<<gE, TB>>>(head);
    k_scan<<<1, 1024>>>();
    k_scatter<<<gE, TB>>>(head, tail);

    // ego0 + acc + tt0; d for iteration 1
    k_init<<<gN16, TB>>>(user, item);
    k_dinit<<<gN4, TB>>>();

    //            xsel dsel ttsel first mode
    k_fused<<<gN16, TB>>>(0, 0, 0, 1, 0, out);   // layer0 iter1
    k_fused<<<gN16, TB>>>(0, 1, 0, 0, 1, out);   // layer0 iter2: acc+, tt1
    k_fused<<<gN16, TB>>>(1, 0, 1, 0, 0, out);   // layer1 iter1
    k_fused<<<gN16, TB>>>(1, 1, 1, 0, 2, out);   // layer1 iter2: out
}